// round 1
// baseline (speedup 1.0000x reference)
#include <cuda_runtime.h>
#include <cstdint>
#include <cstddef>

#define IMG 256
#define HW  65536
#define NF  64
#define NB  8
#define NL  15
#define CH  8

// ---------------- scratch (device globals; no allocation allowed) ----------------
__device__ float g_xpre[(size_t)NB * HW];                 // 2 MB
__device__ float g_h0[(size_t)NB * NF * HW];              // 128 MB
__device__ float g_h1[(size_t)NB * NF * HW];              // 128 MB
__device__ float g_stats[NL * NF * 2];                    // sum, sumsq per layer/channel
__device__ float g_scale[NL * NF];
__device__ float g_shift[NL * NF];

// ---------------- zero the stats buffer (atomics accumulate into it) -------------
__global__ void zero_stats_k() {
    int i = blockIdx.x * blockDim.x + threadIdx.x;
    if (i < NL * NF * 2) g_stats[i] = 0.f;
}

// ---------------- preprocessing: gamma blend + 5x5 bilateral (reflect pad) -------
__global__ __launch_bounds__(256) void preprocess_k(const float* __restrict__ x) {
    __shared__ float t[20][20];
    int tx = threadIdx.x & 15, ty = threadIdx.x >> 4;
    int x0 = blockIdx.x * 16, y0 = blockIdx.y * 16, b = blockIdx.z;
    const float* xb = x + (size_t)b * HW;
    for (int i = threadIdx.x; i < 400; i += 256) {
        int yy = i / 20, xx = i % 20;
        int gy = y0 + yy - 2, gx = x0 + xx - 2;
        if (gy < 0) gy = -gy;
        if (gy > 255) gy = 510 - gy;
        if (gx < 0) gx = -gx;
        if (gx > 255) gx = 510 - gx;
        float v = xb[gy * IMG + gx];
        float xn = (v + 1.f) * 0.5f;
        xn = fminf(fmaxf(xn, 1e-6f), 1.f);
        // blended = (1-ALPHA)*img + ALPHA*img^1.5,  ALPHA=0.4
        t[yy][xx] = 0.6f * xn + 0.4f * xn * sqrtf(xn);
    }
    __syncthreads();
    float c = t[ty + 2][tx + 2];
    float num = 0.f, den = 0.f;
#pragma unroll
    for (int dy = -2; dy <= 2; dy++)
#pragma unroll
        for (int dx = -2; dx <= 2; dx++) {
            float nb = t[ty + 2 + dy][tx + 2 + dx];
            float d = nb - c;
            // exp(spatial)*exp(color) combined: 1/(2*50^2)=2e-4, 1/(2*0.05^2)=200
            float w = expf(-(float)(dy * dy + dx * dx) * 2.0e-4f - d * d * 200.f);
            num += w * nb;
            den += w;
        }
    g_xpre[(size_t)b * HW + (size_t)(y0 + ty) * IMG + (x0 + tx)] = num / den;
}

// ---------------- init conv: 1 -> 64, 3x3 SAME(zero pad), ReLU --------------------
__global__ __launch_bounds__(256) void conv_init_k(const float* __restrict__ w) {
    __shared__ float in_s[18][18];
    __shared__ __align__(16) float w_s[NF * 12];
    int tx = threadIdx.x & 15, ty = threadIdx.x >> 4;
    int x0 = blockIdx.x * 16, y0 = blockIdx.y * 16, b = blockIdx.z;
    for (int i = threadIdx.x; i < 324; i += 256) {
        int yy = i / 18, xx = i % 18;
        int gy = y0 + yy - 1, gx = x0 + xx - 1;
        float v = 0.f;
        if (gy >= 0 && gy < 256 && gx >= 0 && gx < 256)
            v = g_xpre[(size_t)b * HW + (size_t)gy * IMG + gx];
        in_s[yy][xx] = v;
    }
    for (int i = threadIdx.x; i < NF * 9; i += 256)
        w_s[(i / 9) * 12 + (i % 9)] = w[i];
    __syncthreads();
    float i00 = in_s[ty][tx],     i01 = in_s[ty][tx + 1],     i02 = in_s[ty][tx + 2];
    float i10 = in_s[ty + 1][tx], i11 = in_s[ty + 1][tx + 1], i12 = in_s[ty + 1][tx + 2];
    float i20 = in_s[ty + 2][tx], i21 = in_s[ty + 2][tx + 1], i22 = in_s[ty + 2][tx + 2];
    float* outp = g_h0 + (size_t)b * NF * HW + (size_t)(y0 + ty) * IMG + (x0 + tx);
#pragma unroll
    for (int oc = 0; oc < NF; oc++) {
        float4 wa = *(const float4*)&w_s[oc * 12];
        float4 wb = *(const float4*)&w_s[oc * 12 + 4];
        float  wc = w_s[oc * 12 + 8];
        float a = i00 * wa.x + i01 * wa.y + i02 * wa.z + i10 * wa.w +
                  i11 * wb.x + i12 * wb.y + i20 * wb.z + i21 * wb.w + i22 * wc;
        outp[(size_t)oc * HW] = fmaxf(a, 0.f);
    }
}

// ---------------- body conv: 64->64, fused input-BN+ReLU, output ReLU + stats ----
__global__ __launch_bounds__(256, 2) void conv_body_k(const float* __restrict__ w, int l) {
    __shared__ float in_s[CH][18][18];
    __shared__ __align__(16) float w_s[CH * NF * 12];
    __shared__ float red_s[2][NF][8];

    const float* in  = (l & 1) ? g_h1 : g_h0;
    float*       out = (l & 1) ? g_h0 : g_h1;
    const float* sc = (l > 0) ? &g_scale[(l - 1) * NF] : nullptr;
    const float* sh = (l > 0) ? &g_shift[(l - 1) * NF] : nullptr;
    float* stats = &g_stats[l * NF * 2];

    int tx = threadIdx.x & 15, ty = threadIdx.x >> 4;
    int x0 = blockIdx.x * 16, y0 = blockIdx.y * 16, b = blockIdx.z;
    const float* inb = in + (size_t)b * NF * HW;

    float acc[NF];
#pragma unroll
    for (int i = 0; i < NF; i++) acc[i] = 0.f;

    for (int c0 = 0; c0 < NF; c0 += CH) {
        // stage input tile (with previous layer's BN+ReLU applied on the fly)
        for (int i = threadIdx.x; i < CH * 324; i += 256) {
            int c = i / 324, r = i % 324, yy = r / 18, xx = r % 18;
            int gy = y0 + yy - 1, gx = x0 + xx - 1;
            float v = 0.f;
            if (gy >= 0 && gy < 256 && gx >= 0 && gx < 256) {
                v = inb[(size_t)(c0 + c) * HW + (size_t)gy * IMG + gx];
                if (sc) v = fmaxf(v * sc[c0 + c] + sh[c0 + c], 0.f);
            }
            in_s[c][yy][xx] = v;
        }
        // stage weights, padded to 12 floats per (ic,oc) for LDS.128
        for (int i = threadIdx.x; i < NF * CH * 9; i += 256) {
            int oc = i / (CH * 9), r = i % (CH * 9), icl = r / 9, k = r % 9;
            w_s[(icl * NF + oc) * 12 + k] = w[oc * (NF * 9) + (c0 + icl) * 9 + k];
        }
        __syncthreads();
#pragma unroll 1
        for (int icl = 0; icl < CH; icl++) {
            float i00 = in_s[icl][ty][tx],     i01 = in_s[icl][ty][tx + 1],     i02 = in_s[icl][ty][tx + 2];
            float i10 = in_s[icl][ty + 1][tx], i11 = in_s[icl][ty + 1][tx + 1], i12 = in_s[icl][ty + 1][tx + 2];
            float i20 = in_s[icl][ty + 2][tx], i21 = in_s[icl][ty + 2][tx + 1], i22 = in_s[icl][ty + 2][tx + 2];
            const float* wp = &w_s[icl * NF * 12];
#pragma unroll
            for (int oc = 0; oc < NF; oc++) {
                float4 wa = *(const float4*)(wp + oc * 12);
                float4 wb = *(const float4*)(wp + oc * 12 + 4);
                float  wc = wp[oc * 12 + 8];
                acc[oc] += i00 * wa.x + i01 * wa.y + i02 * wa.z + i10 * wa.w +
                           i11 * wb.x + i12 * wb.y + i20 * wb.z + i21 * wb.w + i22 * wc;
            }
        }
        __syncthreads();
    }

    // epilogue: ReLU + store + per-channel (sum, sumsq) reduction
    int lane = threadIdx.x & 31, wid = threadIdx.x >> 5;
    float* outp = out + (size_t)b * NF * HW + (size_t)(y0 + ty) * IMG + (x0 + tx);
#pragma unroll
    for (int oc = 0; oc < NF; oc++) {
        float v = fmaxf(acc[oc], 0.f);
        outp[(size_t)oc * HW] = v;
        float s = v, q = v * v;
#pragma unroll
        for (int off = 16; off; off >>= 1) {
            s += __shfl_down_sync(0xffffffffu, s, off);
            q += __shfl_down_sync(0xffffffffu, q, off);
        }
        if (lane == 0) { red_s[0][oc][wid] = s; red_s[1][oc][wid] = q; }
    }
    __syncthreads();
    if (threadIdx.x < 128) {
        int oc = threadIdx.x & 63, which = threadIdx.x >> 6;
        float t = 0.f;
#pragma unroll
        for (int wd = 0; wd < 8; wd++) t += red_s[which][oc][wd];
        atomicAdd(&stats[oc * 2 + which], t);
    }
}

// ---------------- BN finalize: stats -> per-channel scale/shift -------------------
__global__ void bn_finalize_k(const float* __restrict__ gam, const float* __restrict__ bet, int l) {
    int c = threadIdx.x;
    if (c >= NF) return;
    const float n = (float)((size_t)NB * HW);
    float s = g_stats[l * NF * 2 + c * 2];
    float q = g_stats[l * NF * 2 + c * 2 + 1];
    float mean = s / n;
    float var = q / n - mean * mean;
    float rs = rsqrtf(var + 1e-5f);
    float scl = gam[c] * rs;
    g_scale[l * NF + c] = scl;
    g_shift[l * NF + c] = bet[c] - mean * scl;
}

// ---------------- final conv: 64->1 (input BN+ReLU fused), out = xpre - noise ----
__global__ __launch_bounds__(256) void conv_final_k(const float* __restrict__ w, float* __restrict__ outp) {
    __shared__ float in_s[CH][18][18];
    __shared__ __align__(16) float w_s[NF * 12];
    int tx = threadIdx.x & 15, ty = threadIdx.x >> 4;
    int x0 = blockIdx.x * 16, y0 = blockIdx.y * 16, b = blockIdx.z;
    const float* inb = g_h1 + (size_t)b * NF * HW;  // layer 14 output lives in g_h1
    const float* sc = &g_scale[(NL - 1) * NF];
    const float* sh = &g_shift[(NL - 1) * NF];
    for (int i = threadIdx.x; i < NF * 9; i += 256)
        w_s[(i / 9) * 12 + (i % 9)] = w[i];
    float acc = 0.f;
    for (int c0 = 0; c0 < NF; c0 += CH) {
        for (int i = threadIdx.x; i < CH * 324; i += 256) {
            int c = i / 324, r = i % 324, yy = r / 18, xx = r % 18;
            int gy = y0 + yy - 1, gx = x0 + xx - 1;
            float v = 0.f;
            if (gy >= 0 && gy < 256 && gx >= 0 && gx < 256) {
                v = inb[(size_t)(c0 + c) * HW + (size_t)gy * IMG + gx];
                v = fmaxf(v * sc[c0 + c] + sh[c0 + c], 0.f);
            }
            in_s[c][yy][xx] = v;
        }
        __syncthreads();  // also covers the w_s staging on the first iteration
#pragma unroll
        for (int icl = 0; icl < CH; icl++) {
            float i00 = in_s[icl][ty][tx],     i01 = in_s[icl][ty][tx + 1],     i02 = in_s[icl][ty][tx + 2];
            float i10 = in_s[icl][ty + 1][tx], i11 = in_s[icl][ty + 1][tx + 1], i12 = in_s[icl][ty + 1][tx + 2];
            float i20 = in_s[icl][ty + 2][tx], i21 = in_s[icl][ty + 2][tx + 1], i22 = in_s[icl][ty + 2][tx + 2];
            float4 wa = *(const float4*)&w_s[(c0 + icl) * 12];
            float4 wb = *(const float4*)&w_s[(c0 + icl) * 12 + 4];
            float  wc = w_s[(c0 + icl) * 12 + 8];
            acc += i00 * wa.x + i01 * wa.y + i02 * wa.z + i10 * wa.w +
                   i11 * wb.x + i12 * wb.y + i20 * wb.z + i21 * wb.w + i22 * wc;
        }
        __syncthreads();
    }
    size_t o = (size_t)b * HW + (size_t)(y0 + ty) * IMG + (x0 + tx);
    outp[o] = g_xpre[o] - acc;
}

// ---------------- launch ----------------------------------------------------------
extern "C" void kernel_launch(void* const* d_in, const int* in_sizes, int n_in,
                              void* d_out, int out_size) {
    const float* x       = (const float*)d_in[0];
    const float* w_init  = (const float*)d_in[1];
    const float* w_body  = (const float*)d_in[2];
    const float* bn_g    = (const float*)d_in[3];
    const float* bn_b    = (const float*)d_in[4];
    const float* w_final = (const float*)d_in[5];
    float* out = (float*)d_out;

    dim3 grid(16, 16, NB), blk(256);
    zero_stats_k<<<8, 256>>>();
    preprocess_k<<<grid, blk>>>(x);
    conv_init_k<<<grid, blk>>>(w_init);
    for (int l = 0; l < NL; l++) {
        conv_body_k<<<grid, blk>>>(w_body + (size_t)l * NF * NF * 9, l);
        bn_finalize_k<<<1, 64>>>(bn_g + l * NF, bn_b + l * NF, l);
    }
    conv_final_k<<<grid, blk>>>(w_final, out);
}

// round 9
// speedup vs baseline: 1.2809x; 1.2809x over previous
#include <cuda_runtime.h>
#include <cstdint>
#include <cstddef>

#define IMG 256
#define HW  65536
#define NF  64
#define NB  8
#define NL  15
#define CH  8

// ---------------- scratch (device globals; no allocation allowed) ----------------
__device__ float g_xpre[(size_t)NB * HW];                  // 2 MB
__device__ float g_h0[(size_t)NB * NF * HW];               // 128 MB
__device__ float g_h1[(size_t)NB * NF * HW];               // 128 MB
__device__ float g_stats[NL * NF * 2];                     // float, as in R1
__device__ float g_scale[NL * NF];
__device__ float g_shift[NL * NF];
// weights pre-arranged per (layer, ic-chunk) in R1's exact smem layout:
// g_wp[l][chunk][(icl*NF + oc)*12 + k] = w[l][oc][chunk*8+icl][k]  (k<9; pad 0)
__device__ float g_wp[(size_t)NL * 8 * CH * NF * 12];      // ~2.9 MB

// ---------------- zero the stats buffer -------------------------------------------
__global__ void zero_stats_k() {
    int i = blockIdx.x * blockDim.x + threadIdx.x;
    if (i < NL * NF * 2) g_stats[i] = 0.f;
}

// ---------------- weight pre-arrange (bit-exact copy into R1's smem layout) -------
__global__ void wprep_k(const float* __restrict__ w) {
    int i = blockIdx.x * blockDim.x + threadIdx.x;
    if (i >= NL * 8 * CH * NF * 12) return;
    int l     = i / (8 * CH * NF * 12);
    int r     = i % (8 * CH * NF * 12);
    int chunk = r / (CH * NF * 12);
    int j     = r % (CH * NF * 12);
    int icl   = j / (NF * 12);
    int j2    = j % (NF * 12);
    int oc    = j2 / 12;
    int k     = j2 % 12;
    float v = 0.f;
    if (k < 9)
        v = w[(((size_t)l * NF + oc) * NF + (chunk * CH + icl)) * 9 + k];
    g_wp[i] = v;
}

// ---------------- preprocessing (R1 source, verbatim) ------------------------------
__global__ __launch_bounds__(256) void preprocess_k(const float* __restrict__ x) {
    __shared__ float t[20][20];
    int tx = threadIdx.x & 15, ty = threadIdx.x >> 4;
    int x0 = blockIdx.x * 16, y0 = blockIdx.y * 16, b = blockIdx.z;
    const float* xb = x + (size_t)b * HW;
    for (int i = threadIdx.x; i < 400; i += 256) {
        int yy = i / 20, xx = i % 20;
        int gy = y0 + yy - 2, gx = x0 + xx - 2;
        if (gy < 0) gy = -gy;
        if (gy > 255) gy = 510 - gy;
        if (gx < 0) gx = -gx;
        if (gx > 255) gx = 510 - gx;
        float v = xb[gy * IMG + gx];
        float xn = (v + 1.f) * 0.5f;
        xn = fminf(fmaxf(xn, 1e-6f), 1.f);
        t[yy][xx] = 0.6f * xn + 0.4f * xn * sqrtf(xn);
    }
    __syncthreads();
    float c = t[ty + 2][tx + 2];
    float num = 0.f, den = 0.f;
#pragma unroll
    for (int dy = -2; dy <= 2; dy++)
#pragma unroll
        for (int dx = -2; dx <= 2; dx++) {
            float nb = t[ty + 2 + dy][tx + 2 + dx];
            float d = nb - c;
            float w = expf(-(float)(dy * dy + dx * dx) * 2.0e-4f - d * d * 200.f);
            num += w * nb;
            den += w;
        }
    g_xpre[(size_t)b * HW + (size_t)(y0 + ty) * IMG + (x0 + tx)] = num / den;
}

// ---------------- init conv (R1 source, verbatim) ----------------------------------
__global__ __launch_bounds__(256) void conv_init_k(const float* __restrict__ w) {
    __shared__ float in_s[18][18];
    __shared__ __align__(16) float w_s[NF * 12];
    int tx = threadIdx.x & 15, ty = threadIdx.x >> 4;
    int x0 = blockIdx.x * 16, y0 = blockIdx.y * 16, b = blockIdx.z;
    for (int i = threadIdx.x; i < 324; i += 256) {
        int yy = i / 18, xx = i % 18;
        int gy = y0 + yy - 1, gx = x0 + xx - 1;
        float v = 0.f;
        if (gy >= 0 && gy < 256 && gx >= 0 && gx < 256)
            v = g_xpre[(size_t)b * HW + (size_t)gy * IMG + gx];
        in_s[yy][xx] = v;
    }
    for (int i = threadIdx.x; i < NF * 9; i += 256)
        w_s[(i / 9) * 12 + (i % 9)] = w[i];
    __syncthreads();
    float i00 = in_s[ty][tx],     i01 = in_s[ty][tx + 1],     i02 = in_s[ty][tx + 2];
    float i10 = in_s[ty + 1][tx], i11 = in_s[ty + 1][tx + 1], i12 = in_s[ty + 1][tx + 2];
    float i20 = in_s[ty + 2][tx], i21 = in_s[ty + 2][tx + 1], i22 = in_s[ty + 2][tx + 2];
    float* outp = g_h0 + (size_t)b * NF * HW + (size_t)(y0 + ty) * IMG + (x0 + tx);
#pragma unroll
    for (int oc = 0; oc < NF; oc++) {
        float4 wa = *(const float4*)&w_s[oc * 12];
        float4 wb = *(const float4*)&w_s[oc * 12 + 4];
        float  wc = w_s[oc * 12 + 8];
        float a = i00 * wa.x + i01 * wa.y + i02 * wa.z + i10 * wa.w +
                  i11 * wb.x + i12 * wb.y + i20 * wb.z + i21 * wb.w + i22 * wc;
        outp[(size_t)oc * HW] = fmaxf(a, 0.f);
    }
}

// ---------------- body conv: R1 numerics, 4px x 16oc compute mapping --------------
// Per-output FP expression and BN fold are R1's source verbatim; stats reduction
// is routed through smem to reproduce R1's exact thread mapping + shuffle tree.
__global__ __launch_bounds__(256) void conv_body_k(int l) {
    __shared__ float in_s[CH][18][20];                     // same values as R1 (18x18 live)
    __shared__ __align__(16) float w_s[CH * NF * 12];      // R1 layout: (icl*NF+oc)*12+k
    __shared__ float red_s[2][NF][8];                      // R1 layout
    __shared__ float val_s[16][16];                        // epilogue remap buffer

    const float* in  = (l & 1) ? g_h1 : g_h0;
    float*       out = (l & 1) ? g_h0 : g_h1;
    const float* sc = (l > 0) ? &g_scale[(l - 1) * NF] : nullptr;
    const float* sh = (l > 0) ? &g_shift[(l - 1) * NF] : nullptr;
    float* stats = &g_stats[l * NF * 2];

    int tid = threadIdx.x;
    int ocg = tid >> 6, pid = tid & 63;
    int row = pid >> 2, cg = pid & 3;
    int x0 = blockIdx.x * 16, y0 = blockIdx.y * 16, b = blockIdx.z;
    const float* inb = in + (size_t)b * NF * HW;

    float acc[4][16];
#pragma unroll
    for (int px = 0; px < 4; px++)
#pragma unroll
        for (int j = 0; j < 16; j++) acc[px][j] = 0.f;

    for (int c0 = 0; c0 < NF; c0 += CH) {
        // stage input tile: R1's BN-apply source (same expression, same values)
        for (int i = tid; i < CH * 324; i += 256) {
            int c = i / 324, r2 = i % 324, yy = r2 / 18, xx = r2 % 18;
            int gy = y0 + yy - 1, gx = x0 + xx - 1;
            float v = 0.f;
            if (gy >= 0 && gy < 256 && gx >= 0 && gx < 256) {
                v = inb[(size_t)(c0 + c) * HW + (size_t)gy * IMG + gx];
                if (sc) v = fmaxf(v * sc[c0 + c] + sh[c0 + c], 0.f);
            }
            in_s[c][yy][xx] = v;
        }
        // stage weights: contiguous coalesced copy; smem contents identical to R1
        {
            const float* src = g_wp + ((size_t)l * 8 + (c0 >> 3)) * (CH * NF * 12);
            for (int i = tid; i < CH * NF * 12; i += 256) w_s[i] = src[i];
        }
        __syncthreads();
#pragma unroll 1
        for (int icl = 0; icl < CH; icl++) {
            const float* p = &in_s[icl][row][cg * 4];
            float4 a0 = *(const float4*)p;        float2 b0 = *(const float2*)(p + 4);
            float4 a1 = *(const float4*)(p + 20); float2 b1 = *(const float2*)(p + 24);
            float4 a2 = *(const float4*)(p + 40); float2 b2 = *(const float2*)(p + 44);
            float r0[6] = {a0.x, a0.y, a0.z, a0.w, b0.x, b0.y};
            float r1[6] = {a1.x, a1.y, a1.z, a1.w, b1.x, b1.y};
            float r2[6] = {a2.x, a2.y, a2.z, a2.w, b2.x, b2.y};
#pragma unroll
            for (int j = 0; j < 16; j++) {
                int oc = ocg * 16 + j;
                float4 wa = *(const float4*)&w_s[(icl * NF + oc) * 12];
                float4 wb = *(const float4*)&w_s[(icl * NF + oc) * 12 + 4];
                float  wc = w_s[(icl * NF + oc) * 12 + 8];
#pragma unroll
                for (int px = 0; px < 4; px++) {
                    // R1's exact expression shape (same contraction pattern)
                    acc[px][j] += r0[px] * wa.x + r0[px + 1] * wa.y + r0[px + 2] * wa.z +
                                  r1[px] * wa.w + r1[px + 1] * wb.x + r1[px + 2] * wb.y +
                                  r2[px] * wb.z + r2[px + 1] * wb.w + r2[px + 2] * wc;
                }
            }
        }
        __syncthreads();
    }

    // epilogue 1: ReLU + store (bit-neutral; value set identical to R1's)
    float pr[4][16];
    size_t pbase = (size_t)b * NF * HW + (size_t)(y0 + row) * IMG + (x0 + cg * 4);
#pragma unroll
    for (int j = 0; j < 16; j++) {
        pr[0][j] = fmaxf(acc[0][j], 0.f);
        pr[1][j] = fmaxf(acc[1][j], 0.f);
        pr[2][j] = fmaxf(acc[2][j], 0.f);
        pr[3][j] = fmaxf(acc[3][j], 0.f);
        int oc = ocg * 16 + j;
        *(float4*)(out + pbase + (size_t)oc * HW) =
            make_float4(pr[0][j], pr[1][j], pr[2][j], pr[3][j]);
    }

    // epilogue 2: stats in R1's EXACT reduction order (remap via smem per oc)
    int tx = tid & 15, ty = tid >> 4;       // R1 thread->pixel mapping
    int lane = tid & 31, wid8 = tid >> 5;   // R1 warp structure (8 warps)
    for (int oc = 0; oc < NF; oc++) {
        int og = oc >> 4, j = oc & 15;
        __syncthreads();
        if (ocg == og) {
#pragma unroll
            for (int px = 0; px < 4; px++) val_s[row][cg * 4 + px] = pr[px][j];
        }
        __syncthreads();
        float v = val_s[ty][tx];
        float s = v, q = v * v;
#pragma unroll
        for (int off = 16; off; off >>= 1) {
            s += __shfl_down_sync(0xffffffffu, s, off);
            q += __shfl_down_sync(0xffffffffu, q, off);
        }
        if (lane == 0) { red_s[0][oc][wid8] = s; red_s[1][oc][wid8] = q; }
    }
    __syncthreads();
    if (tid < 128) {
        int oc = tid & 63, which = tid >> 6;
        float t = 0.f;
#pragma unroll
        for (int wd = 0; wd < 8; wd++) t += red_s[which][oc][wd];
        atomicAdd(&stats[oc * 2 + which], t);
    }
}

// ---------------- BN finalize (R1 source, verbatim) --------------------------------
__global__ void bn_finalize_k(const float* __restrict__ gam, const float* __restrict__ bet, int l) {
    int c = threadIdx.x;
    if (c >= NF) return;
    const float n = (float)((size_t)NB * HW);
    float s = g_stats[l * NF * 2 + c * 2];
    float q = g_stats[l * NF * 2 + c * 2 + 1];
    float mean = s / n;
    float var = q / n - mean * mean;
    float rs = rsqrtf(var + 1e-5f);
    float scl = gam[c] * rs;
    g_scale[l * NF + c] = scl;
    g_shift[l * NF + c] = bet[c] - mean * scl;
}

// ---------------- final conv (R1 source, verbatim) ---------------------------------
__global__ __launch_bounds__(256) void conv_final_k(const float* __restrict__ w, float* __restrict__ outp) {
    __shared__ float in_s[CH][18][18];
    __shared__ __align__(16) float w_s[NF * 12];
    int tx = threadIdx.x & 15, ty = threadIdx.x >> 4;
    int x0 = blockIdx.x * 16, y0 = blockIdx.y * 16, b = blockIdx.z;
    const float* inb = g_h1 + (size_t)b * NF * HW;  // layer 14 output lives in g_h1
    const float* sc = &g_scale[(NL - 1) * NF];
    const float* sh = &g_shift[(NL - 1) * NF];
    for (int i = threadIdx.x; i < NF * 9; i += 256)
        w_s[(i / 9) * 12 + (i % 9)] = w[i];
    float acc = 0.f;
    for (int c0 = 0; c0 < NF; c0 += CH) {
        for (int i = threadIdx.x; i < CH * 324; i += 256) {
            int c = i / 324, r = i % 324, yy = r / 18, xx = r % 18;
            int gy = y0 + yy - 1, gx = x0 + xx - 1;
            float v = 0.f;
            if (gy >= 0 && gy < 256 && gx >= 0 && gx < 256) {
                v = inb[(size_t)(c0 + c) * HW + (size_t)gy * IMG + gx];
                v = fmaxf(v * sc[c0 + c] + sh[c0 + c], 0.f);
            }
            in_s[c][yy][xx] = v;
        }
        __syncthreads();
#pragma unroll
        for (int icl = 0; icl < CH; icl++) {
            float i00 = in_s[icl][ty][tx],     i01 = in_s[icl][ty][tx + 1],     i02 = in_s[icl][ty][tx + 2];
            float i10 = in_s[icl][ty + 1][tx], i11 = in_s[icl][ty + 1][tx + 1], i12 = in_s[icl][ty + 1][tx + 2];
            float i20 = in_s[icl][ty + 2][tx], i21 = in_s[icl][ty + 2][tx + 1], i22 = in_s[icl][ty + 2][tx + 2];
            float4 wa = *(const float4*)&w_s[(c0 + icl) * 12];
            float4 wb = *(const float4*)&w_s[(c0 + icl) * 12 + 4];
            float  wc = w_s[(c0 + icl) * 12 + 8];
            acc += i00 * wa.x + i01 * wa.y + i02 * wa.z + i10 * wa.w +
                   i11 * wb.x + i12 * wb.y + i20 * wb.z + i21 * wb.w + i22 * wc;
        }
        __syncthreads();
    }
    size_t o = (size_t)b * HW + (size_t)(y0 + ty) * IMG + (x0 + tx);
    outp[o] = g_xpre[o] - acc;
}

// ---------------- launch ----------------------------------------------------------
extern "C" void kernel_launch(void* const* d_in, const int* in_sizes, int n_in,
                              void* d_out, int out_size) {
    const float* x       = (const float*)d_in[0];
    const float* w_init  = (const float*)d_in[1];
    const float* w_body  = (const float*)d_in[2];
    const float* bn_g    = (const float*)d_in[3];
    const float* bn_b    = (const float*)d_in[4];
    const float* w_final = (const float*)d_in[5];
    float* out = (float*)d_out;

    dim3 grid(16, 16, NB), blk(256);
    zero_stats_k<<<8, 256>>>();
    wprep_k<<<(NL * 8 * CH * NF * 12 + 255) / 256, 256>>>(w_body);
    preprocess_k<<<grid, blk>>>(x);
    conv_init_k<<<grid, blk>>>(w_init);
    for (int l = 0; l < NL; l++) {
        conv_body_k<<<grid, blk>>>(l);
        bn_finalize_k<<<1, 64>>>(bn_g + l * NF, bn_b + l * NF, l);
    }
    conv_final_k<<<grid, blk>>>(w_final, out);
}